// round 14
// baseline (speedup 1.0000x reference)
#include <cuda_runtime.h>

#define IMG 28
#define PIX 784
#define QUADS 196
#define B_IMGS 65536
#define CENTER 14
#define NIMG 8
#define NUM_T 20
#define COPY_BLOCKS 6272          // (65536/8)*196/256  (exact)
#define FIX_BLOCKS 1024           // 65536 images / (8 warps * 8 imgs/warp)
#define GRID_BLOCKS 8192          // every 8th block is a fixup block

__global__ __launch_bounds__(256)
void sr_split_kernel(const float* __restrict__ x, const int* __restrict__ t,
                     const float* __restrict__ Wk, const float* __restrict__ bias,
                     float* __restrict__ out)
{
    __shared__ unsigned short s_list[PIX];
    __shared__ int s_off[NUM_T + 1];
    __shared__ int s_cur[NUM_T];

    unsigned bid = blockIdx.x;
    bool is_fix = (bid & 7u) == 0u;

    if (is_fix) {
        // ---------------- FIXUP ROLE: conv on exactly the active pixels ----------------
        unsigned fix_id = bid >> 3;            // 0..1023
        int tid = threadIdx.x;

        if (tid < NUM_T) s_cur[tid] = 0;
        __syncthreads();

        int ts_arr[4];
#pragma unroll
        for (int it = 0; it < 4; it++) {
            int pix = tid + it * 256;
            int tstar = 255;
            if (pix < PIX) {
                int r = pix / IMG, c = pix - (pix / IMG) * IMG;
                int dr = r - CENTER, dc = c - CENTER;
                int d2 = dr * dr + dc * dc;
                int s = (int)sqrtf((float)d2);
                while (s * s < d2) s++;                      // s = ceil(sqrt(d2))
                while (s > 0 && (s - 1) * (s - 1) >= d2) s--;
                tstar = s;                                   // unique active t for this pixel
            }
            ts_arr[it] = tstar;
            if (tstar < NUM_T) atomicAdd(&s_cur[tstar], 1);
        }
        __syncthreads();
        if (tid == 0) {
            int acc = 0;
            for (int k = 0; k < NUM_T; k++) { s_off[k] = acc; acc += s_cur[k]; }
            s_off[NUM_T] = acc;
        }
        __syncthreads();
        if (tid < NUM_T) s_cur[tid] = s_off[tid];
        __syncthreads();
#pragma unroll
        for (int it = 0; it < 4; it++) {
            int pix = tid + it * 256;
            int tstar = ts_arr[it];
            if (pix < PIX && tstar < NUM_T) {
                int pos = atomicAdd(&s_cur[tstar], 1);       // order-free: pixels disjoint
                s_list[pos] = (unsigned short)pix;
            }
        }
        __syncthreads();

        float w[9];
#pragma unroll
        for (int j = 0; j < 9; j++) w[j] = __ldg(Wk + j);
        float bb = __ldg(bias);

        int wid = tid >> 5, lane = tid & 31;
#pragma unroll 1
        for (int j = 0; j < 8; j++) {
            int img = (int)fix_id * 64 + wid * 8 + j;
            int tv = __ldg(t + img);
            if (tv < 0 || tv >= NUM_T) continue;
            int beg = s_off[tv], end = s_off[tv + 1];
            const float* ximg = x + (size_t)img * PIX;
            float* oimg = out + (size_t)img * PIX;
            for (int i = beg + lane; i < end; i += 32) {
                int pix = s_list[i];
                int r = pix / IMG, c = pix - (pix / IMG) * IMG;
                float acc = bb;
#pragma unroll
                for (int rr = -1; rr <= 1; rr++) {
                    int r2 = r + rr;
                    if (r2 >= 0 && r2 < IMG) {
#pragma unroll
                        for (int cc = -1; cc <= 1; cc++) {
                            int c2 = c + cc;
                            if (c2 >= 0 && c2 < IMG)
                                acc = fmaf(w[(rr + 1) * 3 + (cc + 1)],
                                           __ldg(ximg + r2 * IMG + c2), acc);
                        }
                    }
                }
                oimg[pix] = __ldg(ximg + pix) + acc;   // out = x + x0 on active pixel
            }
        }
        return;
    }

    // ---------------- COPY ROLE: pure streaming, conv-free ----------------
    unsigned copy_id = bid - (bid >> 3) - 1u;          // dense id over non-fix blocks
    if (copy_id >= COPY_BLOCKS) return;                // few spare tail blocks idle

    unsigned idx = copy_id * 256u + threadIdx.x;
    unsigned grp = idx / QUADS;
    unsigned quad = idx - grp * QUADS;
    unsigned img0 = grp * NIMG;

    unsigned row = quad / 7u;
    unsigned col0 = (quad - row * 7u) * 4u;
    int dr = (int)row - CENTER;
    int dr2 = dr * dr;
    int d2[4];
#pragma unroll
    for (int k = 0; k < 4; k++) {
        int dc = (int)col0 + k - CENTER;
        d2[k] = dr2 + dc * dc;
    }
    int d2min = min(min(d2[0], d2[1]), min(d2[2], d2[3]));
    int d2max = max(max(d2[0], d2[1]), max(d2[2], d2[3]));
    int tlo = (int)sqrtf((float)d2min);        // <= min t*  (safe superset)
    int thi = (int)sqrtf((float)d2max) + 1;    // >= max t*  (safe superset)

    const float* xq = x   + (size_t)img0 * PIX + quad * 4;
    float*       oq = out + (size_t)img0 * PIX + quad * 4;

    int4 tva = *reinterpret_cast<const int4*>(t + img0);      // img0 % 8 == 0 -> aligned
    int4 tvb = *reinterpret_cast<const int4*>(t + img0 + 4);
    int tv[8] = {tva.x, tva.y, tva.z, tva.w, tvb.x, tvb.y, tvb.z, tvb.w};

#pragma unroll
    for (int i = 0; i < NIMG; i++) {
        float4 v = *reinterpret_cast<const float4*>(xq + i * PIX);
        int tt = tv[i];
        if (tt < tlo || tt > thi) {
            *reinterpret_cast<float4*>(oq + i * PIX) = v;     // fast path: full quad
        } else {
            // quad may contain active pixels: store only the inactive ones
            int r2max = tt * tt;
            int r2min = (tt >= 1) ? (tt - 1) * (tt - 1) : -1;
            float* op = oq + i * PIX;
            const float* vv = reinterpret_cast<const float*>(&v);
#pragma unroll
            for (int k = 0; k < 4; k++) {
                bool active = (d2[k] <= r2max) && (d2[k] > r2min);  // exact; matches t* def
                if (!active) op[k] = vv[k];
            }
        }
    }
}

extern "C" void kernel_launch(void* const* d_in, const int* in_sizes, int n_in,
                              void* d_out, int out_size)
{
    const float* x    = (const float*)d_in[0];   // [65536,1,28,28] f32
    const int*   t    = (const int*)  d_in[1];   // [65536] i32
    const float* Wk   = (const float*)d_in[2];   // [1,1,3,3] f32
    const float* bias = (const float*)d_in[3];   // [1] f32
    float* out = (float*)d_out;

    sr_split_kernel<<<GRID_BLOCKS, 256>>>(x, t, Wk, bias, out);
}